// round 6
// baseline (speedup 1.0000x reference)
#include <cuda_runtime.h>
#include <math.h>
#include <stdint.h>

#define BATCH 4
#define CHN   64
#define HH    128
#define WWD   128
#define TILE  16
#define HALO  5
#define SMW   26          // TILE + 2*HALO
#define SMST  27          // padded row stride
#define CCH   8           // channel chunk (arconv, double-buffered)
#define NCHK  (CHN/CCH)   // 8 chunks
#define NPGRP 4           // rf channel groups
#define GCH   16          // channels per rf group

#define WS_FL   (CCH*9*CHN)          // 4608 floats
#define XS_FL   (CCH*SMW*SMST)       // 5616 floats
#define BUF_FL  (WS_FL + XS_FL)      // 10224 floats
#define SMEM_BYTES (2*BUF_FL*4)      // 81792 bytes

// ---------------- device scratch (no allocation allowed) ----------------
__device__ float g_rfp[NPGRP*BATCH*2*HH*WWD]; // per-group partial rf accum (pre-sigmoid)
__device__ float g_t1 [BATCH*CHN*HH*WWD];     // relu(arconv1) intermediate
__device__ __align__(16) float g_wt1[CHN*CHN*9];  // W1 transposed to [c][k][o]
__device__ __align__(16) float g_wt2[CHN*CHN*9];

// ---------------- cp.async helpers ----------------
__device__ __forceinline__ void cp_async4(uint32_t dst, const void* src) {
    asm volatile("cp.async.ca.shared.global [%0], [%1], 4;" :: "r"(dst), "l"(src));
}
__device__ __forceinline__ void cp_async16(uint32_t dst, const void* src) {
    asm volatile("cp.async.cg.shared.global [%0], [%1], 16;" :: "r"(dst), "l"(src));
}
__device__ __forceinline__ void cp_commit() {
    asm volatile("cp.async.commit_group;");
}
__device__ __forceinline__ void cp_wait0() {
    asm volatile("cp.async.wait_group 0;");
}

// ---------------- packed f32x2 helpers ----------------
__device__ __forceinline__ unsigned long long pack2(float v) {
    unsigned long long r;
    asm("mov.b64 %0, {%1, %1};" : "=l"(r) : "r"(__float_as_uint(v)));
    return r;
}
__device__ __forceinline__ void ffma2(unsigned long long& acc,
                                      unsigned long long w,
                                      unsigned long long v) {
    asm("fma.rn.f32x2 %0, %1, %2, %0;" : "+l"(acc) : "l"(w), "l"(v));
}

// ---------------- W transpose: [o][c][k] -> [c][k][o] ----------------
__global__ void transpose_w_kernel(const float* __restrict__ W1,
                                   const float* __restrict__ W2) {
    int i = blockIdx.x * blockDim.x + threadIdx.x;
    if (i >= CHN*CHN*9) return;
    const float* src = blockIdx.y ? W2 : W1;
    float*       dst = blockIdx.y ? g_wt2 : g_wt1;
    int o = i % CHN;
    int k = (i / CHN) % 9;
    int c = i / (CHN*9);
    dst[i] = src[(o*CHN + c)*9 + k];
}

// ---------------- rf partial: 16-channel 3x3 zero-pad conv partial sums ----------------
// grid (8,8,16): z = b*NPGRP + cg. All smem fills batched via cp.async (high MLP).
__global__ __launch_bounds__(256)
void rf_partial_kernel(const float* __restrict__ xin,
                       const float* __restrict__ w_off,
                       int use_t1) {
    __shared__ float wt[2*GCH*9];
    __shared__ float tile[GCH*18*19];

    const float* in = use_t1 ? g_t1 : xin;

    int tid = threadIdx.x;
    int lx = tid & 15, ly = tid >> 4;
    int z  = blockIdx.z;
    int b  = z >> 2;
    int cg = z & 3;
    int c0 = cg * GCH;
    int px = blockIdx.x*TILE + lx;
    int py = blockIdx.y*TILE + ly;
    int ry0 = blockIdx.y*TILE - 1;
    int rx0 = blockIdx.x*TILE - 1;

    uint32_t wt_s   = (uint32_t)__cvta_generic_to_shared(wt);
    uint32_t tile_s = (uint32_t)__cvta_generic_to_shared(tile);

    // weights (cp.async, 4B each; 288 total)
    for (int i = tid; i < 2*GCH*9; i += 256) {
        int comp = i / (GCH*9);
        int rem  = i - comp*(GCH*9);
        cp_async4(wt_s + i*4, w_off + (comp*CHN + c0)*9 + rem);
    }

    // halo-tile positions (18x18 = 324, <=2 per thread)
    int pg[2], ps[2], npos = 0;
    #pragma unroll
    for (int j = 0; j < 2; ++j) {
        int i = tid + 256*j;
        if (i < 18*18) {
            int r = i / 18, col = i - r*18;
            int gy = ry0 + r, gx = rx0 + col;
            bool ok = (gy >= 0 && gy < HH && gx >= 0 && gx < WWD);
            pg[npos] = ok ? gy*WWD + gx : -1;
            ps[npos] = r*19 + col;
            npos++;
        }
    }

    const float* inb = in + ((size_t)b*CHN + c0)*HH*WWD;
    // all 16 channels' tile fills issued back-to-back -> MLP ~32 per thread
    for (int c = 0; c < GCH; ++c) {
        const float* src = inb + (size_t)c*HH*WWD;
        #pragma unroll
        for (int j = 0; j < 2; ++j) {
            if (j < npos) {
                uint32_t d = tile_s + (c*(18*19) + ps[j])*4;
                if (pg[j] >= 0) cp_async4(d, src + pg[j]);
                else            tile[c*(18*19) + ps[j]] = 0.f;
            }
        }
    }
    cp_commit();
    cp_wait0();
    __syncthreads();

    float acc0 = 0.f, acc1 = 0.f;
    #pragma unroll
    for (int c = 0; c < GCH; ++c) {
        const float* t  = tile + c*(18*19);
        const float* w0 = wt + c*9;
        const float* w1 = wt + (GCH + c)*9;
        #pragma unroll
        for (int ky = 0; ky < 3; ++ky)
        #pragma unroll
        for (int kx = 0; kx < 3; ++kx) {
            float v = t[(ly+ky)*19 + lx + kx];
            acc0 = fmaf(v, w0[ky*3+kx], acc0);
            acc1 = fmaf(v, w1[ky*3+kx], acc1);
        }
    }

    size_t base = ((((size_t)cg*BATCH + b)*2 + 0)*HH + py)*WWD + px;
    g_rfp[base]                  = acc0;
    g_rfp[base + (size_t)HH*WWD] = acc1;
}

// ---------------- fused arconv: sigmoid(rf partials) + gather + 64x576 GEMV ----------------
// Double-buffered cp.async pipeline over 8 channel-chunks of 8.
// mode 0: input = xin,  output = g_t1 = relu(conv + b), weights g_wt1
// mode 1: input = g_t1, output = out_ext = xin + conv + b, weights g_wt2
__global__ __launch_bounds__(128, 2)
void arconv_kernel(const float* __restrict__ xin,
                   const float* __restrict__ bias,
                   const float* __restrict__ b_off,
                   const int*   __restrict__ lo_p,
                   const int*   __restrict__ hi_p,
                   float* __restrict__ out_ext,
                   int mode) {
    extern __shared__ float smem[];   // 2 buffers: [ws(4608) | xs(5616)] each

    const float* in = mode ? g_t1  : xin;
    const float* wt = mode ? g_wt2 : g_wt1;

    int tid = threadIdx.x;          // 128 threads
    int lx = tid & 15, ly = tid >> 4;   // ly in 0..7
    int b = blockIdx.z;
    int px = blockIdx.x*TILE + lx;
    int rowbase = blockIdx.y*TILE - HALO;
    int colbase = blockIdx.x*TILE - HALO;

    uint32_t smem_s = (uint32_t)__cvta_generic_to_shared(smem);

    float lo = (float)(*lo_p), hi = (float)(*hi_p);
    float bo0 = b_off[0], bo1 = b_off[1];

    // per-pixel sample geometry for 2 pixels (rows ly and ly+8)
    int   oy0[2][3], oy1[2][3];
    int   sx0[2][3], sx1[2][3];
    float fy[2][3],  fx[2][3];
    int py[2];
    #pragma unroll
    for (int p = 0; p < 2; ++p) {
        py[p] = blockIdx.y*TILE + ly + 8*p;
        size_t pbase = (((size_t)b*2 + 0)*HH + py[p])*WWD + px;
        size_t pstep = (size_t)HH*WWD;
        float z0 = bo0, z1 = bo1;
        #pragma unroll
        for (int g = 0; g < NPGRP; ++g) {
            size_t gofs = (size_t)g*BATCH*2*HH*WWD;
            z0 += g_rfp[gofs + pbase];
            z1 += g_rfp[gofs + pbase + pstep];
        }
        float s0 = 1.f / (1.f + expf(-z0));
        float s1 = 1.f / (1.f + expf(-z1));
        float rh = (lo + (hi - lo)*s0) * 0.5f;
        float rw = (lo + (hi - lo)*s1) * 0.5f;
        #pragma unroll
        for (int i = 0; i < 3; ++i) {
            float dv = (float)(i - 1);
            float ysf = (float)py[p] + dv*rh;
            float yfl = floorf(ysf);
            fy[p][i] = ysf - yfl;
            int y0 = min(max((int)yfl, 0), HH-1);
            int y1 = min(y0 + 1, HH-1);
            oy0[p][i] = (y0 - rowbase)*SMST;
            oy1[p][i] = (y1 - rowbase)*SMST;

            float xsf = (float)px + dv*rw;
            float xfl = floorf(xsf);
            fx[p][i] = xsf - xfl;
            int x0 = min(max((int)xfl, 0), WWD-1);
            int x1 = min(x0 + 1, WWD-1);
            sx0[p][i] = x0 - colbase;
            sx1[p][i] = x1 - colbase;
        }
    }

    // halo-tile fill positions (26x26 = 676, <=6 per thread)
    int fillg[6], fills[6], nfill = 0;
    #pragma unroll
    for (int j = 0; j < 6; ++j) {
        int i = tid + 128*j;
        if (i < SMW*SMW) {
            int r = i / SMW, col = i - r*SMW;
            int gy = min(max(rowbase + r,   0), HH-1);
            int gx = min(max(colbase + col, 0), WWD-1);
            fillg[nfill] = gy*WWD + gx;
            fills[nfill] = r*SMST + col;
            nfill++;
        }
    }

    unsigned long long acc[2][32];
    #pragma unroll
    for (int p = 0; p < 2; ++p)
        #pragma unroll
        for (int i = 0; i < 32; ++i) acc[p][i] = 0ull;

    const float* inb = in + (size_t)b*CHN*HH*WWD;

    // ---- chunk fill via cp.async into buffer bi ----
    // chunk cb covers channels [cb*CCH, (cb+1)*CCH)
    auto fill_chunk = [&](int cb, int bi) {
        uint32_t buf_s = smem_s + bi*(BUF_FL*4);
        // weights: chunk base = cb*CCH channels * 9*CHN floats/channel
        const float* wsrc = wt + (size_t)cb*CCH*9*CHN;
        #pragma unroll
        for (int i = 0; i < 9; ++i) {
            int idx = tid + 128*i;       // float4 index < 1152
            cp_async16(buf_s + idx*16, wsrc + idx*4);
        }
        // input halo tiles: 8 channels x <=6 positions, 4B each
        uint32_t xs_s = buf_s + WS_FL*4;
        #pragma unroll
        for (int c = 0; c < CCH; ++c) {
            const float* src = inb + (size_t)(cb*CCH + c)*HH*WWD;
            uint32_t dst_c = xs_s + c*(SMW*SMST*4);
            #pragma unroll
            for (int j = 0; j < 6; ++j)
                if (j < nfill) cp_async4(dst_c + fills[j]*4, src + fillg[j]);
        }
        cp_commit();
    };

    fill_chunk(0, 0);

    for (int cb = 0; cb < NCHK; ++cb) {
        cp_wait0();
        __syncthreads();
        if (cb + 1 < NCHK) fill_chunk(cb + 1, (cb + 1) & 1);

        const float* buf = smem + (cb & 1)*BUF_FL;
        const float* ws  = buf;
        const float* xs  = buf + WS_FL;

        for (int c = 0; c < CCH; ++c) {
            const float* xc = xs + c*(SMW*SMST);
            const float* wc = ws + c*(9*CHN);
            #pragma unroll
            for (int iy = 0; iy < 3; ++iy) {
                #pragma unroll
                for (int ix = 0; ix < 3; ++ix) {
                    unsigned long long vv0, vv1;
                    {
                        float v00 = xc[oy0[0][iy] + sx0[0][ix]];
                        float v01 = xc[oy0[0][iy] + sx1[0][ix]];
                        float v10 = xc[oy1[0][iy] + sx0[0][ix]];
                        float v11 = xc[oy1[0][iy] + sx1[0][ix]];
                        float fxv = fx[0][ix];
                        float top = fmaf(fxv, v01 - v00, v00);
                        float bot = fmaf(fxv, v11 - v10, v10);
                        vv0 = pack2(fmaf(fy[0][iy], bot - top, top));
                    }
                    {
                        float v00 = xc[oy0[1][iy] + sx0[1][ix]];
                        float v01 = xc[oy0[1][iy] + sx1[1][ix]];
                        float v10 = xc[oy1[1][iy] + sx0[1][ix]];
                        float v11 = xc[oy1[1][iy] + sx1[1][ix]];
                        float fxv = fx[1][ix];
                        float top = fmaf(fxv, v01 - v00, v00);
                        float bot = fmaf(fxv, v11 - v10, v10);
                        vv1 = pack2(fmaf(fy[1][iy], bot - top, top));
                    }
                    const ulonglong2* wp =
                        (const ulonglong2*)(wc + (iy*3 + ix)*CHN);
                    #pragma unroll
                    for (int o4 = 0; o4 < 16; ++o4) {
                        ulonglong2 w2 = wp[o4];     // LDS.128 broadcast
                        ffma2(acc[0][2*o4  ], w2.x, vv0);
                        ffma2(acc[0][2*o4+1], w2.y, vv0);
                        ffma2(acc[1][2*o4  ], w2.x, vv1);
                        ffma2(acc[1][2*o4+1], w2.y, vv1);
                    }
                }
            }
        }
    }

    #pragma unroll
    for (int p = 0; p < 2; ++p) {
        size_t base = (size_t)b*CHN*HH*WWD + (size_t)py[p]*WWD + px;
        if (mode == 0) {
            float* outb = g_t1 + base;
            #pragma unroll
            for (int o2 = 0; o2 < 32; ++o2) {
                float2 a = *(float2*)&acc[p][o2];
                outb[(size_t)(2*o2    )*HH*WWD] = fmaxf(a.x + bias[2*o2],     0.f);
                outb[(size_t)(2*o2 + 1)*HH*WWD] = fmaxf(a.y + bias[2*o2 + 1], 0.f);
            }
        } else {
            float* outb = out_ext + base;
            const float* xb = xin + base;
            #pragma unroll
            for (int o2 = 0; o2 < 32; ++o2) {
                float2 a = *(float2*)&acc[p][o2];
                outb[(size_t)(2*o2    )*HH*WWD] = a.x + bias[2*o2]     + xb[(size_t)(2*o2    )*HH*WWD];
                outb[(size_t)(2*o2 + 1)*HH*WWD] = a.y + bias[2*o2 + 1] + xb[(size_t)(2*o2 + 1)*HH*WWD];
            }
        }
    }
}

// ---------------- launch ----------------
extern "C" void kernel_launch(void* const* d_in, const int* in_sizes, int n_in,
                              void* d_out, int out_size) {
    const float* x      = (const float*)d_in[0];
    const float* w_off1 = (const float*)d_in[1];
    const float* b_off1 = (const float*)d_in[2];
    const float* W1     = (const float*)d_in[3];
    const float* b1     = (const float*)d_in[4];
    const float* w_off2 = (const float*)d_in[5];
    const float* b_off2 = (const float*)d_in[6];
    const float* W2     = (const float*)d_in[7];
    const float* b2     = (const float*)d_in[8];
    const int*   hw_lo  = (const int*)d_in[10];
    const int*   hw_hi  = (const int*)d_in[11];
    float* out = (float*)d_out;

    cudaFuncSetAttribute(arconv_kernel,
                         cudaFuncAttributeMaxDynamicSharedMemorySize, SMEM_BYTES);

    dim3 grid_t((CHN*CHN*9 + 255)/256, 2);
    dim3 grid_s(HH/TILE, WWD/TILE, BATCH);            // 8 x 8 x 4
    dim3 grid_r(HH/TILE, WWD/TILE, BATCH*NPGRP);      // 8 x 8 x 16

    transpose_w_kernel<<<grid_t, 256>>>(W1, W2);

    // arconv 1: rf partials from x, sigmoid fused into arconv, conv(x), relu -> g_t1
    rf_partial_kernel<<<grid_r, 256>>>(x, w_off1, 0);
    arconv_kernel<<<grid_s, 128, SMEM_BYTES>>>(x, b1, b_off1, hw_lo, hw_hi, out, 0);

    // arconv 2: rf partials from g_t1, conv(g_t1), + x -> out
    rf_partial_kernel<<<grid_r, 256>>>(x, w_off2, 1);
    arconv_kernel<<<grid_s, 128, SMEM_BYTES>>>(x, b2, b_off2, hw_lo, hw_hi, out, 1);
}

// round 9
// speedup vs baseline: 1.6681x; 1.6681x over previous
#include <cuda_runtime.h>
#include <math.h>
#include <stdint.h>

#define BATCH 4
#define CHN   64
#define HH    128
#define WWD   128
#define TILE  16
#define HALO  5
#define SMW   26          // TILE + 2*HALO
#define SMST  27          // padded row stride
#define CCH   16          // channel chunk (arconv)
#define NPGRP 4           // rf channel groups
#define GCH   16          // channels per rf group
#define RBAND 8           // rf output rows per CTA
#define RROWS 10          // RBAND + 2 halo rows

#define WS_FLOATS  (CCH*9*CHN)            // 9216
#define XS_FLOATS  (CCH*SMW*SMST)         // 11232
#define SMEM_BYTES ((WS_FLOATS + XS_FLOATS)*4)   // 81792

#define RF_WT_FL   (2*GCH*9)              // 288
#define RF_TILE_FL (GCH*RROWS*WWD)        // 20480
#define RF_SMEM_BYTES ((RF_WT_FL + RF_TILE_FL)*4) // 83072

// ---------------- device scratch (no allocation allowed) ----------------
__device__ float g_rfp[NPGRP*BATCH*2*HH*WWD]; // per-group partial rf accum (pre-sigmoid)
__device__ float g_t1 [BATCH*CHN*HH*WWD];     // relu(arconv1) intermediate
__device__ __align__(16) float g_wt1[CHN*CHN*9];  // W1 transposed to [c][k][o]
__device__ __align__(16) float g_wt2[CHN*CHN*9];

// ---------------- packed f32x2 helpers ----------------
__device__ __forceinline__ unsigned long long pack2(float v) {
    unsigned long long r;
    asm("mov.b64 %0, {%1, %1};" : "=l"(r) : "r"(__float_as_uint(v)));
    return r;
}
__device__ __forceinline__ void ffma2(unsigned long long& acc,
                                      unsigned long long w,
                                      unsigned long long v) {
    asm("fma.rn.f32x2 %0, %1, %2, %0;" : "+l"(acc) : "l"(w), "l"(v));
}

// ---------------- W transpose: [o][c][k] -> [c][k][o] ----------------
__global__ void transpose_w_kernel(const float* __restrict__ W1,
                                   const float* __restrict__ W2) {
    int i = blockIdx.x * blockDim.x + threadIdx.x;
    if (i >= CHN*CHN*9) return;
    const float* src = blockIdx.y ? W2 : W1;
    float*       dst = blockIdx.y ? g_wt2 : g_wt1;
    int o = i % CHN;
    int k = (i / CHN) % 9;
    int c = i / (CHN*9);
    dst[i] = src[(o*CHN + c)*9 + k];
}

// ---------------- rf partial: row-band streaming 3x3 conv partials ----------------
// grid (16, NPGRP, BATCH). CTA loads a 10-row x 128-col x 16-ch band (float4
// coalesced, MLP 20/thread), computes 8 rows x 128 cols x 2 comps of partials.
__global__ __launch_bounds__(256)
void rf_band_kernel(const float* __restrict__ xin,
                    const float* __restrict__ w_off,
                    int use_t1) {
    extern __shared__ float rsm[];
    float* wt   = rsm;                 // [2][GCH][9]
    float* tile = rsm + RF_WT_FL;      // [GCH][RROWS][WWD]

    const float* in = use_t1 ? g_t1 : xin;

    int tid = threadIdx.x;
    int y0  = blockIdx.x * RBAND;
    int cg  = blockIdx.y;
    int b   = blockIdx.z;
    int c0  = cg * GCH;

    // weights for this group's 16 channels, both comps (288 entries, 256 threads)
    for (int i = tid; i < RF_WT_FL; i += 256) {
        int comp = i / (GCH*9);
        int rem  = i - comp*(GCH*9);
        wt[i] = w_off[comp*CHN*9 + c0*9 + rem];
    }

    // band load: 16ch x 10 rows x 128 cols = 5120 float4, 20 per thread
    const float* inb = in + ((size_t)b*CHN + c0)*HH*WWD;
    #pragma unroll
    for (int j = 0; j < 20; ++j) {
        int idx = tid + 256*j;             // < 5120
        int c   = idx / 320;               // 320 float4 per channel (10*32)
        int rem = idx - c*320;
        int r   = rem >> 5;                // row 0..9
        int xq  = rem & 31;                // float4 col
        int gy  = y0 - 1 + r;
        float4 v = make_float4(0.f, 0.f, 0.f, 0.f);
        if (gy >= 0 && gy < HH)
            v = *(const float4*)(inb + ((size_t)c*HH + gy)*WWD + xq*4);
        *(float4*)(tile + (c*RROWS + r)*WWD + xq*4) = v;
    }
    __syncthreads();

    // compute: 256 threads -> x = tid&127, row pairs rbase, rbase+2, +4, +6
    int x = tid & 127;
    int rbase = tid >> 7;                  // 0 or 1
    bool xm = (x > 0), xp = (x < WWD-1);

    float acc0[4] = {0.f,0.f,0.f,0.f};
    float acc1[4] = {0.f,0.f,0.f,0.f};

    for (int c = 0; c < GCH; ++c) {
        const float* tc = tile + c*(RROWS*WWD);
        const float* w0 = wt + c*9;
        const float* w1 = wt + GCH*9 + c*9;
        #pragma unroll
        for (int p = 0; p < 4; ++p) {
            int rr = rbase + 2*p;          // smem row of top of 3x3 window
            #pragma unroll
            for (int dr = 0; dr < 3; ++dr) {
                const float* row = tc + (rr+dr)*WWD;
                float vm = xm ? row[x-1] : 0.f;
                float v0 = row[x];
                float vp = xp ? row[x+1] : 0.f;
                acc0[p] = fmaf(vm, w0[dr*3+0], acc0[p]);
                acc0[p] = fmaf(v0, w0[dr*3+1], acc0[p]);
                acc0[p] = fmaf(vp, w0[dr*3+2], acc0[p]);
                acc1[p] = fmaf(vm, w1[dr*3+0], acc1[p]);
                acc1[p] = fmaf(v0, w1[dr*3+1], acc1[p]);
                acc1[p] = fmaf(vp, w1[dr*3+2], acc1[p]);
            }
        }
    }

    #pragma unroll
    for (int p = 0; p < 4; ++p) {
        int y = y0 + rbase + 2*p;
        size_t base = ((((size_t)cg*BATCH + b)*2 + 0)*HH + y)*WWD + x;
        g_rfp[base]                  = acc0[p];
        g_rfp[base + (size_t)HH*WWD] = acc1[p];
    }
}

// ---------------- fused arconv: sigmoid(rf partials) + gather + 64x576 GEMV ----------------
// mode 0: input = xin,  output = g_t1 = relu(conv + b), weights g_wt1
// mode 1: input = g_t1, output = out_ext = xin + conv + b, weights g_wt2
__global__ __launch_bounds__(128, 2)
void arconv_kernel(const float* __restrict__ xin,
                   const float* __restrict__ bias,
                   const float* __restrict__ b_off,
                   const int*   __restrict__ lo_p,
                   const int*   __restrict__ hi_p,
                   float* __restrict__ out_ext,
                   int mode) {
    extern __shared__ float smem[];
    float* ws = smem;               // [CCH][9][CHN]  16B-aligned rows
    float* xs = smem + WS_FLOATS;   // [CCH][SMW][SMST]

    const float* in = mode ? g_t1  : xin;
    const float* wt = mode ? g_wt2 : g_wt1;

    int tid = threadIdx.x;          // 128 threads
    int lx = tid & 15, ly = tid >> 4;   // ly in 0..7
    int b = blockIdx.z;
    int px = blockIdx.x*TILE + lx;
    int rowbase = blockIdx.y*TILE - HALO;
    int colbase = blockIdx.x*TILE - HALO;

    float lo = (float)(*lo_p), hi = (float)(*hi_p);
    float bo0 = b_off[0], bo1 = b_off[1];

    // per-pixel sample geometry for the 2 pixels (rows ly and ly+8)
    int   oy0[2][3], oy1[2][3];
    int   sx0[2][3], sx1[2][3];
    float fy[2][3],  fx[2][3];
    int py[2];
    #pragma unroll
    for (int p = 0; p < 2; ++p) {
        py[p] = blockIdx.y*TILE + ly + 8*p;
        size_t pbase = (((size_t)b*2 + 0)*HH + py[p])*WWD + px;
        size_t pstep = (size_t)HH*WWD;
        float z0 = bo0, z1 = bo1;
        #pragma unroll
        for (int g = 0; g < NPGRP; ++g) {
            size_t gofs = (size_t)g*BATCH*2*HH*WWD;
            z0 += g_rfp[gofs + pbase];
            z1 += g_rfp[gofs + pbase + pstep];
        }
        float s0 = 1.f / (1.f + expf(-z0));
        float s1 = 1.f / (1.f + expf(-z1));
        float rh = (lo + (hi - lo)*s0) * 0.5f;
        float rw = (lo + (hi - lo)*s1) * 0.5f;
        #pragma unroll
        for (int i = 0; i < 3; ++i) {
            float dv = (float)(i - 1);
            float ysf = (float)py[p] + dv*rh;
            float yfl = floorf(ysf);
            fy[p][i] = ysf - yfl;
            int y0 = min(max((int)yfl, 0), HH-1);
            int y1 = min(y0 + 1, HH-1);
            oy0[p][i] = (y0 - rowbase)*SMST;
            oy1[p][i] = (y1 - rowbase)*SMST;

            float xsf = (float)px + dv*rw;
            float xfl = floorf(xsf);
            fx[p][i] = xsf - xfl;
            int x0 = min(max((int)xfl, 0), WWD-1);
            int x1 = min(x0 + 1, WWD-1);
            sx0[p][i] = x0 - colbase;
            sx1[p][i] = x1 - colbase;
        }
    }

    // precompute this thread's halo-tile fill positions (26x26 = 676, <=6 per thread)
    int fillg[6], fills[6], nfill = 0;
    #pragma unroll
    for (int j = 0; j < 6; ++j) {
        int i = tid + 128*j;
        if (i < SMW*SMW) {
            int r = i / SMW, col = i - r*SMW;
            int gy = min(max(rowbase + r,   0), HH-1);
            int gx = min(max(colbase + col, 0), WWD-1);
            fillg[nfill] = gy*WWD + gx;
            fills[nfill] = r*SMST + col;
            nfill++;
        }
    }

    unsigned long long acc[2][32];
    #pragma unroll
    for (int p = 0; p < 2; ++p)
        #pragma unroll
        for (int i = 0; i < 32; ++i) acc[p][i] = 0ull;

    const float* inb = in + (size_t)b*CHN*HH*WWD;

    for (int cb = 0; cb < CHN; cb += CCH) {
        __syncthreads();
        // weights chunk: float4 coalesced copy
        const float4* wsrc4 = (const float4*)(wt + cb*9*CHN);
        float4*       ws4   = (float4*)ws;
        #pragma unroll 6
        for (int i = tid; i < WS_FLOATS/4; i += 128) ws4[i] = wsrc4[i];
        // haloed input tile via precomputed positions (no div/mod)
        #pragma unroll 4
        for (int c = 0; c < CCH; ++c) {
            const float* src = inb + (size_t)(cb + c)*HH*WWD;
            float* dst = xs + c*(SMW*SMST);
            #pragma unroll
            for (int j = 0; j < 6; ++j)
                if (j < nfill) dst[fills[j]] = src[fillg[j]];
        }
        __syncthreads();

        for (int c = 0; c < CCH; ++c) {
            const float* xc = xs + c*(SMW*SMST);
            const float* wc = ws + c*9*CHN;
            #pragma unroll
            for (int iy = 0; iy < 3; ++iy) {
                #pragma unroll
                for (int ix = 0; ix < 3; ++ix) {
                    unsigned long long vv0, vv1;
                    {
                        float v00 = xc[oy0[0][iy] + sx0[0][ix]];
                        float v01 = xc[oy0[0][iy] + sx1[0][ix]];
                        float v10 = xc[oy1[0][iy] + sx0[0][ix]];
                        float v11 = xc[oy1[0][iy] + sx1[0][ix]];
                        float fxv = fx[0][ix];
                        float top = fmaf(fxv, v01 - v00, v00);
                        float bot = fmaf(fxv, v11 - v10, v10);
                        vv0 = pack2(fmaf(fy[0][iy], bot - top, top));
                    }
                    {
                        float v00 = xc[oy0[1][iy] + sx0[1][ix]];
                        float v01 = xc[oy0[1][iy] + sx1[1][ix]];
                        float v10 = xc[oy1[1][iy] + sx0[1][ix]];
                        float v11 = xc[oy1[1][iy] + sx1[1][ix]];
                        float fxv = fx[1][ix];
                        float top = fmaf(fxv, v01 - v00, v00);
                        float bot = fmaf(fxv, v11 - v10, v10);
                        vv1 = pack2(fmaf(fy[1][iy], bot - top, top));
                    }
                    const ulonglong2* wp =
                        (const ulonglong2*)(wc + (iy*3 + ix)*CHN);
                    #pragma unroll
                    for (int o4 = 0; o4 < 16; ++o4) {
                        ulonglong2 w2 = wp[o4];     // LDS.128 broadcast
                        ffma2(acc[0][2*o4  ], w2.x, vv0);
                        ffma2(acc[0][2*o4+1], w2.y, vv0);
                        ffma2(acc[1][2*o4  ], w2.x, vv1);
                        ffma2(acc[1][2*o4+1], w2.y, vv1);
                    }
                }
            }
        }
    }

    #pragma unroll
    for (int p = 0; p < 2; ++p) {
        size_t base = (size_t)b*CHN*HH*WWD + (size_t)py[p]*WWD + px;
        if (mode == 0) {
            float* outb = g_t1 + base;
            #pragma unroll
            for (int o2 = 0; o2 < 32; ++o2) {
                float2 a = *(float2*)&acc[p][o2];
                outb[(size_t)(2*o2    )*HH*WWD] = fmaxf(a.x + bias[2*o2],     0.f);
                outb[(size_t)(2*o2 + 1)*HH*WWD] = fmaxf(a.y + bias[2*o2 + 1], 0.f);
            }
        } else {
            float* outb = out_ext + base;
            const float* xb = xin + base;
            #pragma unroll
            for (int o2 = 0; o2 < 32; ++o2) {
                float2 a = *(float2*)&acc[p][o2];
                outb[(size_t)(2*o2    )*HH*WWD] = a.x + bias[2*o2]     + xb[(size_t)(2*o2    )*HH*WWD];
                outb[(size_t)(2*o2 + 1)*HH*WWD] = a.y + bias[2*o2 + 1] + xb[(size_t)(2*o2 + 1)*HH*WWD];
            }
        }
    }
}

// ---------------- launch ----------------
extern "C" void kernel_launch(void* const* d_in, const int* in_sizes, int n_in,
                              void* d_out, int out_size) {
    const float* x      = (const float*)d_in[0];
    const float* w_off1 = (const float*)d_in[1];
    const float* b_off1 = (const float*)d_in[2];
    const float* W1     = (const float*)d_in[3];
    const float* b1     = (const float*)d_in[4];
    const float* w_off2 = (const float*)d_in[5];
    const float* b_off2 = (const float*)d_in[6];
    const float* W2     = (const float*)d_in[7];
    const float* b2     = (const float*)d_in[8];
    const int*   hw_lo  = (const int*)d_in[10];
    const int*   hw_hi  = (const int*)d_in[11];
    float* out = (float*)d_out;

    cudaFuncSetAttribute(arconv_kernel,
                         cudaFuncAttributeMaxDynamicSharedMemorySize, SMEM_BYTES);
    cudaFuncSetAttribute(rf_band_kernel,
                         cudaFuncAttributeMaxDynamicSharedMemorySize, RF_SMEM_BYTES);

    dim3 grid_t((CHN*CHN*9 + 255)/256, 2);
    dim3 grid_s(HH/TILE, WWD/TILE, BATCH);            // 8 x 8 x 4
    dim3 grid_r(HH/RBAND, NPGRP, BATCH);              // 16 x 4 x 4

    transpose_w_kernel<<<grid_t, 256>>>(W1, W2);

    // arconv 1: rf partials from x, sigmoid fused into arconv, conv(x), relu -> g_t1
    rf_band_kernel<<<grid_r, 256, RF_SMEM_BYTES>>>(x, w_off1, 0);
    arconv_kernel<<<grid_s, 128, SMEM_BYTES>>>(x, b1, b_off1, hw_lo, hw_hi, out, 0);

    // arconv 2: rf partials from g_t1, conv(g_t1), + x -> out
    rf_band_kernel<<<grid_r, 256, RF_SMEM_BYTES>>>(x, w_off2, 1);
    arconv_kernel<<<grid_s, 128, SMEM_BYTES>>>(x, b2, b_off2, hw_lo, hw_hi, out, 1);
}